// round 8
// baseline (speedup 1.0000x reference)
#include <cuda_runtime.h>
#include <math.h>

#define Nn 512
#define Bb 8
#define Cc 64
#define Hh 64
#define Tt 16
#define Ll 2
#define Ee 16384
#define NB (Nn*Bb)          /* 4096 rows for gate GEMMs */
#define MAT (NB*Hh)         /* 262144 floats per [N,B,H] matrix */
#define NCTAS 256

typedef unsigned long long u64;

// ---------------- device scratch ----------------
__device__ float g_S[Nn*Nn];
__device__ float g_S2[Nn*Nn];
__device__ float g_deg[Nn];
__device__ float g_dinv[Nn];
__device__ float g_U[(long)Tt*3*MAT];
__device__ float g_Xc[(long)Tt*Ll*3*MAT];
__device__ float g_h[MAT];
__device__ float g_z[MAT];
__device__ float g_hr[MAT];
__device__ float g_T1[MAT];
__device__ float g_T2[MAT];
__device__ float g_sp[MAT];
__device__ float g_tp[MAT];
__device__ int   g_idx32;
__device__ unsigned g_barCount;
__device__ unsigned g_barPhase;

// ---------------- f32x2 helpers ----------------
__device__ __forceinline__ u64 ffma2(u64 a, u64 b, u64 c) {
    u64 d;
    asm("fma.rn.f32x2 %0, %1, %2, %3;" : "=l"(d) : "l"(a), "l"(b), "l"(c));
    return d;
}
__device__ __forceinline__ u64 splat2(float x) {
    u64 r;
    asm("mov.b64 %0, {%1, %1};" : "=l"(r) : "r"(__float_as_uint(x)));
    return r;
}
__device__ __forceinline__ float2 u2f(u64 v) {
    float2 f;
    asm("mov.b64 {%0, %1}, %2;" : "=f"(f.x), "=f"(f.y) : "l"(v));
    return f;
}

// ---------------- grid barrier (persistent kernel) ----------------
__device__ __forceinline__ unsigned ld_acq(unsigned* p) {
    unsigned v;
    asm volatile("ld.acquire.gpu.u32 %0, [%1];" : "=r"(v) : "l"(p) : "memory");
    return v;
}
__device__ __forceinline__ void st_rel(unsigned* p, unsigned v) {
    asm volatile("st.release.gpu.u32 [%0], %1;" :: "l"(p), "r"(v) : "memory");
}
__device__ __forceinline__ unsigned atom_add_acqrel(unsigned* p, unsigned v) {
    unsigned old;
    asm volatile("atom.acq_rel.gpu.add.u32 %0, [%1], %2;" : "=r"(old) : "l"(p), "r"(v) : "memory");
    return old;
}
__device__ __forceinline__ void grid_bar(unsigned& phase) {
    __syncthreads();
    phase += 1;
    if (threadIdx.x == 0) {
        unsigned old = atom_add_acqrel(&g_barCount, 1u);
        if (old == NCTAS - 1) {
            g_barCount = 0;
            st_rel(&g_barPhase, phase);
        } else {
            while (ld_acq(&g_barPhase) < phase) { __nanosleep(64); }
        }
    }
    __syncthreads();
}

// ---------------- shared memory (one buffer, unioned per phase) ----------------
struct SmemG {
    __align__(16) u64   As2[2][32][34];  // [buf][k][m] splatted {a,a}
    __align__(16) float Bs[2][32][64];   // [buf][k][n]
};
struct SmemP {
    float sps[32][65];
    float tps[32][65];
    float w2[64];
};
union SmemBuf { SmemG g; SmemP p; };

// ---------------- dtype probe + init/graph build (separate tiny nodes) ----------------
__global__ void probe_kernel(const void* __restrict__ ei) {
    const long long* p = (const long long*)ei;
    int is64 = 1;
    for (int i = 0; i < 64; i++) {
        long long v = p[i];
        if (v < 0 || v >= (long long)Nn) { is64 = 0; break; }
    }
    g_idx32 = is64 ? 0 : 1;
}
__device__ __forceinline__ int load_idx(const void* ei, long i) {
    if (g_idx32) return ((const int*)ei)[i];
    return (int)(((const long long*)ei)[i]);
}
__global__ void zero_init_kernel() {
    int i = blockIdx.x * blockDim.x + threadIdx.x;
    if (i < Nn*Nn) g_S[i] = 0.0f;
    if (i < MAT)   g_h[i] = 0.0f;
    if (i < Nn)    g_deg[i] = 0.0f;
    if (i == 0) { g_barCount = 0; g_barPhase = 0; }
}
__global__ void deg_kernel(const void* __restrict__ ei, const float* __restrict__ w) {
    int e = blockIdx.x * blockDim.x + threadIdx.x;
    if (e < Ee) atomicAdd(&g_deg[load_idx(ei, e)], w[e]);
}
__global__ void dinv_kernel() {
    int i = blockIdx.x * blockDim.x + threadIdx.x;
    if (i < Nn) {
        float d = g_deg[i];
        g_dinv[i] = (d > 0.0f) ? rsqrtf(fmaxf(d, 1e-12f)) : 0.0f;
    }
}
__global__ void scatterS_kernel(const void* __restrict__ ei, const float* __restrict__ w) {
    int e = blockIdx.x * blockDim.x + threadIdx.x;
    if (e < Ee) {
        int s = load_idx(ei, e);
        int d = load_idx(ei, (long)Ee + e);
        atomicAdd(&g_S[(long)d * Nn + s], -w[e] * g_dinv[s] * g_dinv[d]);
    }
}

// ============ K=512 GEMM core: O = alpha * M @ X + beta * Y (tile 32x64) ============
__device__ __forceinline__ void gemm512_core(
        SmemG& s, const float* __restrict__ M, const float* __restrict__ X,
        const float* __restrict__ Y, float* __restrict__ O,
        float alpha, float beta, int mBase, int nBase) {
    int tid = threadIdx.x;
    int tx = tid & 15, ty = tid >> 4;
    int lm  = tid >> 3;
    int lk4 = (tid & 7) << 2;
    int bk  = tid >> 4;
    int bn4 = (tid & 15) << 2;

    float4 a_reg, b_reg0, b_reg1;

    a_reg  = *(const float4*)&M[(long)(mBase + lm) * 512 + lk4];
    b_reg0 = *(const float4*)&X[(long)bk * 512 + nBase + bn4];
    b_reg1 = *(const float4*)&X[(long)(16 + bk) * 512 + nBase + bn4];
    s.As2[0][lk4+0][lm] = splat2(a_reg.x); s.As2[0][lk4+1][lm] = splat2(a_reg.y);
    s.As2[0][lk4+2][lm] = splat2(a_reg.z); s.As2[0][lk4+3][lm] = splat2(a_reg.w);
    *(float4*)&s.Bs[0][bk][bn4] = b_reg0;
    *(float4*)&s.Bs[0][bk+16][bn4] = b_reg1;
    __syncthreads();

    u64 acc[2][2] = {{0ull, 0ull}, {0ull, 0ull}};

    for (int t = 0; t < 16; t++) {
        int cur = t & 1, nxt = cur ^ 1;
        if (t < 15) {
            int kk = (t + 1) * 32;
            a_reg  = *(const float4*)&M[(long)(mBase + lm) * 512 + kk + lk4];
            b_reg0 = *(const float4*)&X[(long)(kk + bk) * 512 + nBase + bn4];
            b_reg1 = *(const float4*)&X[(long)(kk + 16 + bk) * 512 + nBase + bn4];
        }
        #pragma unroll
        for (int k = 0; k < 32; k++) {
            ulonglong2 a2 = *(const ulonglong2*)&s.As2[cur][k][ty * 2];
            ulonglong2 b2 = *(const ulonglong2*)&s.Bs[cur][k][tx * 4];
            acc[0][0] = ffma2(a2.x, b2.x, acc[0][0]);
            acc[0][1] = ffma2(a2.x, b2.y, acc[0][1]);
            acc[1][0] = ffma2(a2.y, b2.x, acc[1][0]);
            acc[1][1] = ffma2(a2.y, b2.y, acc[1][1]);
        }
        if (t < 15) {
            s.As2[nxt][lk4+0][lm] = splat2(a_reg.x); s.As2[nxt][lk4+1][lm] = splat2(a_reg.y);
            s.As2[nxt][lk4+2][lm] = splat2(a_reg.z); s.As2[nxt][lk4+3][lm] = splat2(a_reg.w);
            *(float4*)&s.Bs[nxt][bk][bn4] = b_reg0;
            *(float4*)&s.Bs[nxt][bk+16][bn4] = b_reg1;
        }
        __syncthreads();
    }

    #pragma unroll
    for (int i = 0; i < 2; i++) {
        long r = mBase + ty * 2 + i;
        long off = r * 512 + nBase + tx * 4;
        float2 lo = u2f(acc[i][0]), hi = u2f(acc[i][1]);
        float4 v;
        v.x = alpha * lo.x; v.y = alpha * lo.y;
        v.z = alpha * hi.x; v.w = alpha * hi.y;
        if (Y) {
            float4 y = *(const float4*)&Y[off];
            v.x += beta * y.x; v.y += beta * y.y; v.z += beta * y.z; v.w += beta * y.w;
        }
        *(float4*)&O[off] = v;
    }
}

// ============ small GEMM core: acc += sum over ntiles of A_p tile @ W tile ============
__device__ __forceinline__ void mm64_core(
        SmemG& s, const float* __restrict__ A0, const float* __restrict__ A1,
        const float* __restrict__ A2, const float* __restrict__ W,
        int ntiles, int mBase, u64 (&acc)[2][2]) {
    int tid = threadIdx.x;
    int tx = tid & 15, ty = tid >> 4;
    int lm  = tid >> 3;
    int lk4 = (tid & 7) << 2;
    int bk  = tid >> 4;
    int bn4 = (tid & 15) << 2;

    const float* Aps[3] = {A0, A1, A2};
    float4 a_reg, b_reg0, b_reg1;

    a_reg  = *(const float4*)&A0[(long)(mBase + lm) * 64 + lk4];
    b_reg0 = *(const float4*)&W[(long)bk * 64 + bn4];
    b_reg1 = *(const float4*)&W[(long)(16 + bk) * 64 + bn4];
    s.As2[0][lk4+0][lm] = splat2(a_reg.x); s.As2[0][lk4+1][lm] = splat2(a_reg.y);
    s.As2[0][lk4+2][lm] = splat2(a_reg.z); s.As2[0][lk4+3][lm] = splat2(a_reg.w);
    *(float4*)&s.Bs[0][bk][bn4] = b_reg0;
    *(float4*)&s.Bs[0][bk+16][bn4] = b_reg1;
    __syncthreads();

    for (int tile = 0; tile < ntiles; tile++) {
        int cur = tile & 1, nxt = cur ^ 1;
        if (tile + 1 < ntiles) {
            int p  = (tile + 1) >> 1;
            int kk = ((tile + 1) & 1) * 32;
            const float* A = Aps[p];
            int wr = p * 64 + kk;
            a_reg  = *(const float4*)&A[(long)(mBase + lm) * 64 + kk + lk4];
            b_reg0 = *(const float4*)&W[(long)(wr + bk) * 64 + bn4];
            b_reg1 = *(const float4*)&W[(long)(wr + 16 + bk) * 64 + bn4];
        }
        #pragma unroll
        for (int k = 0; k < 32; k++) {
            ulonglong2 a2 = *(const ulonglong2*)&s.As2[cur][k][ty * 2];
            ulonglong2 b2 = *(const ulonglong2*)&s.Bs[cur][k][tx * 4];
            acc[0][0] = ffma2(a2.x, b2.x, acc[0][0]);
            acc[0][1] = ffma2(a2.x, b2.y, acc[0][1]);
            acc[1][0] = ffma2(a2.y, b2.x, acc[1][0]);
            acc[1][1] = ffma2(a2.y, b2.y, acc[1][1]);
        }
        if (tile + 1 < ntiles) {
            s.As2[nxt][lk4+0][lm] = splat2(a_reg.x); s.As2[nxt][lk4+1][lm] = splat2(a_reg.y);
            s.As2[nxt][lk4+2][lm] = splat2(a_reg.z); s.As2[nxt][lk4+3][lm] = splat2(a_reg.w);
            *(float4*)&s.Bs[nxt][bk][bn4] = b_reg0;
            *(float4*)&s.Bs[nxt][bk+16][bn4] = b_reg1;
        }
        __syncthreads();
    }
}

// gate epilogue: g==0: z=sigmoid; g==1: hr=h*sigmoid; g==2: h=z*h+(1-z)*tanh
__device__ __forceinline__ void gate_epilogue(u64 (&acc)[2][2], int g, int mBase,
                                              const float* __restrict__ Xc) {
    int tid = threadIdx.x;
    int tx = tid & 15, ty = tid >> 4;
    int c = tx * 4;
    #pragma unroll
    for (int i = 0; i < 2; i++) {
        long r = mBase + ty * 2 + i;
        long off = r * 64 + c;
        float4 xc = *(const float4*)&Xc[off];
        float2 lo = u2f(acc[i][0]), hi = u2f(acc[i][1]);
        float v0 = lo.x + xc.x, v1 = lo.y + xc.y;
        float v2 = hi.x + xc.z, v3 = hi.y + xc.w;
        if (g == 0) {
            float4 o;
            o.x = 1.0f / (1.0f + expf(-v0)); o.y = 1.0f / (1.0f + expf(-v1));
            o.z = 1.0f / (1.0f + expf(-v2)); o.w = 1.0f / (1.0f + expf(-v3));
            *(float4*)&g_z[off] = o;
        } else if (g == 1) {
            float4 hv = *(const float4*)&g_h[off];
            float4 o;
            o.x = hv.x / (1.0f + expf(-v0)); o.y = hv.y / (1.0f + expf(-v1));
            o.z = hv.z / (1.0f + expf(-v2)); o.w = hv.w / (1.0f + expf(-v3));
            *(float4*)&g_hr[off] = o;
        } else {
            float4 hv = *(const float4*)&g_h[off];
            float4 zv = *(const float4*)&g_z[off];
            float4 o;
            o.x = zv.x * hv.x + (1.0f - zv.x) * tanhf(v0);
            o.y = zv.y * hv.y + (1.0f - zv.y) * tanhf(v1);
            o.z = zv.z * hv.z + (1.0f - zv.z) * tanhf(v2);
            o.w = zv.w * hv.w + (1.0f - zv.w) * tanhf(v3);
            *(float4*)&g_h[off] = o;
        }
    }
}

// predict one 32x32 (s,t) tile for batch b. 256 threads, 4 outputs each.
__device__ __forceinline__ void predict_tile(
        SmemP& s, int b, int sBase, int tBase,
        const float* __restrict__ b1, const float* __restrict__ W2,
        const float* __restrict__ b2, float* __restrict__ out) {
    int tid = threadIdx.x;
    __syncthreads();   // protect smem vs previous tile's readers
    for (int i = tid; i < 2048; i += 256) {
        int r = i >> 6, cc = i & 63;
        s.sps[r][cc] = g_sp[((long)(sBase + r) * Bb + b) * Hh + cc] + b1[cc];
        s.tps[r][cc] = g_tp[((long)(tBase + r) * Bb + b) * Hh + cc];
    }
    if (tid < 64) s.w2[tid] = W2[tid];
    __syncthreads();

    int tx = tid & 31, ty = tid >> 5;   // ty 0..7
    float bias = b2[0];
    float a0 = bias, a1 = bias, a2 = bias, a3 = bias;
    #pragma unroll
    for (int hh = 0; hh < 64; hh++) {
        float tv = s.tps[tx][hh];
        float w  = s.w2[hh];
        a0 += fmaxf(s.sps[ty +  0][hh] + tv, 0.0f) * w;
        a1 += fmaxf(s.sps[ty +  8][hh] + tv, 0.0f) * w;
        a2 += fmaxf(s.sps[ty + 16][hh] + tv, 0.0f) * w;
        a3 += fmaxf(s.sps[ty + 24][hh] + tv, 0.0f) * w;
    }
    long rowBase = (long)b * Nn * Nn + (long)tBase + tx;
    out[rowBase + (long)(sBase + ty +  0) * Nn] = a0;
    out[rowBase + (long)(sBase + ty +  8) * Nn] = a1;
    out[rowBase + (long)(sBase + ty + 16) * Nn] = a2;
    out[rowBase + (long)(sBase + ty + 24) * Nn] = a3;
}

// ============ THE MEGA KERNEL: everything after graph build, one node ============
__global__ __launch_bounds__(256, 2) void mega_kernel(
        const float* __restrict__ x,
        const float* __restrict__ Wx, const float* __restrict__ bx,
        const float* __restrict__ Wh, const float* __restrict__ bh,
        const float* __restrict__ W1, const float* __restrict__ b1,
        const float* __restrict__ W2, const float* __restrict__ b2,
        float* __restrict__ out) {
    __shared__ SmemBuf sm;
    const int c = blockIdx.x;
    const int tid = threadIdx.x;
    unsigned bph = 0;

    const int c128  = c & 127;
    const int mB512 = (c128 >> 3) * 32;   // 16 m-tiles of 32 rows
    const int nB512 = (c128 & 7) * 64;    // 8 n-tiles of 64 cols
    const int mB64  = (c >> 1) * 32;      // 128 row-tiles for [4096,64] GEMMs

    // ---- Phase A: S2 = S @ S (CTAs 0..127) | permute x -> U0 (CTAs 128..255) ----
    if (c < 128) {
        gemm512_core(sm.g, g_S, g_S, (const float*)0, g_S2, 1.0f, 0.0f, mB512, nB512);
    } else {
        long base = (long)(c - 128) * 32768;
        for (long i = base + tid; i < base + 32768; i += 256) {
            int cc = (int)(i & 63);
            long r = i >> 6;
            int n = (int)(r % Nn); r /= Nn;
            int t = (int)(r % Tt);
            int b = (int)(r / Tt);
            g_U[((long)(t*3) * NB + (long)n * Bb + b) * Hh + cc] = x[i];
        }
    }
    grid_bar(bph);

    // ---- Phase B: x-basis. CTA keeps one fixed 512-tile across all 16 t. ----
    {
        int w = c & 1;
        int tileId = c >> 1;
        int mB = (tileId >> 3) * 32, nB = (tileId & 7) * 64;
        for (int t = 0; t < Tt; t++) {
            const float* U0 = g_U + (long)(t*3) * MAT;
            if (w == 0)
                gemm512_core(sm.g, g_S,  U0, (const float*)0, g_U + (long)(t*3+1)*MAT, 1.0f,  0.0f, mB, nB);
            else
                gemm512_core(sm.g, g_S2, U0, U0,              g_U + (long)(t*3+2)*MAT, 2.0f, -1.0f, mB, nB);
        }
    }
    grid_bar(bph);

    // ---- Phase C: Xc[t][l][g] = sum_k U[t][k] @ Wx[l][g][k] + bx + bh ----
    {
        int lgbase = (c & 1) * 3;
        for (int t = 0; t < Tt; t++) {
            const float* A0 = g_U + (long)(t*3 + 0) * MAT;
            const float* A1 = g_U + (long)(t*3 + 1) * MAT;
            const float* A2 = g_U + (long)(t*3 + 2) * MAT;
            for (int gg = 0; gg < 3; gg++) {
                int lg = lgbase + gg;
                u64 acc[2][2] = {{0ull,0ull},{0ull,0ull}};
                mm64_core(sm.g, A0, A1, A2, Wx + (long)lg * 3 * (Cc*Hh), 6, mB64, acc);
                // epilogue with summed biases
                int tx = tid & 15, ty = tid >> 4;
                int cc = tx * 4;
                float* o = g_Xc + ((long)(t*Ll + lg/3) * 3 + (lg % 3)) * MAT;
                float b0 = bx[lg*Hh + cc+0] + bh[lg*Hh + cc+0];
                float b1v = bx[lg*Hh + cc+1] + bh[lg*Hh + cc+1];
                float b2v = bx[lg*Hh + cc+2] + bh[lg*Hh + cc+2];
                float b3 = bx[lg*Hh + cc+3] + bh[lg*Hh + cc+3];
                #pragma unroll
                for (int i = 0; i < 2; i++) {
                    long r = mB64 + ty * 2 + i;
                    float2 lo = u2f(acc[i][0]), hi = u2f(acc[i][1]);
                    float4 v;
                    v.x = lo.x + b0; v.y = lo.y + b1v; v.z = hi.x + b2v; v.w = hi.y + b3;
                    *(float4*)&o[r * 64 + cc] = v;
                }
            }
        }
    }
    grid_bar(bph);

    // ---- Phase D: recurrent chain, 32 cells x 4 stages. Fixed tiles per CTA. ----
    for (int cell = 0; cell < Tt * Ll; cell++) {
        int t = cell >> 1, l = cell & 1;
        const float* Wl    = Wh + (long)l * 9 * (Hh*Hh);
        const float* Xc_tl = g_Xc + ((long)(t*Ll + l) * 3) * MAT;

        // stage 1: T1 = S h | T2 = 2 S2 h - h
        if (c < 128) gemm512_core(sm.g, g_S,  g_h, (const float*)0, g_T1, 1.0f,  0.0f, mB512, nB512);
        else         gemm512_core(sm.g, g_S2, g_h, g_h,             g_T2, 2.0f, -1.0f, mB512, nB512);
        grid_bar(bph);

        // stage 2: gates z (even CTAs) / r->hr (odd CTAs)
        {
            int g = c & 1;
            u64 acc[2][2] = {{0ull,0ull},{0ull,0ull}};
            mm64_core(sm.g, g_h, g_T1, g_T2, Wl + (long)g * 3 * (Hh*Hh), 6, mB64, acc);
            gate_epilogue(acc, g, mB64, Xc_tl + (long)g * MAT);
        }
        grid_bar(bph);

        // stage 3: T1 = S hr | T2 = 2 S2 hr - hr
        if (c < 128) gemm512_core(sm.g, g_S,  g_hr, (const float*)0, g_T1, 1.0f,  0.0f, mB512, nB512);
        else         gemm512_core(sm.g, g_S2, g_hr, g_hr,            g_T2, 2.0f, -1.0f, mB512, nB512);
        grid_bar(bph);

        // stage 4: h~ gate + GRU update (CTAs 0..127)
        if (c < 128) {
            u64 acc[2][2] = {{0ull,0ull},{0ull,0ull}};
            mm64_core(sm.g, g_hr, g_T1, g_T2, Wl + (long)2 * 3 * (Hh*Hh), 6, c * 32, acc);
            gate_epilogue(acc, 2, c * 32, Xc_tl + (long)2 * MAT);
        }
        grid_bar(bph);
    }

    // ---- Phase E: sp/tp projections ----
    {
        int half = c & 1;
        u64 acc[2][2] = {{0ull,0ull},{0ull,0ull}};
        mm64_core(sm.g, g_h, g_h, g_h, W1 + (long)half * (Hh*Hh), 2, mB64, acc);
        int tx = tid & 15, ty = tid >> 4;
        float* o = half ? g_tp : g_sp;
        #pragma unroll
        for (int i = 0; i < 2; i++) {
            long r = mB64 + ty * 2 + i;
            float2 lo = u2f(acc[i][0]), hi = u2f(acc[i][1]);
            float4 v; v.x = lo.x; v.y = lo.y; v.z = hi.x; v.w = hi.y;
            *(float4*)&o[r * 64 + tx * 4] = v;
        }
    }
    grid_bar(bph);

    // ---- Phase F: all-pairs logits, 8 tiles per CTA ----
    for (int i = 0; i < 8; i++) {
        int unit = c * 8 + i;              // 0..2047
        int b  = unit & 7;
        int sT = (unit >> 3) & 15;
        int tT = (unit >> 7) & 15;
        predict_tile(sm.p, b, sT * 32, tT * 32, b1, W2, b2, out);
    }
}

// ---------------- host-side orchestration: exactly 6 graph nodes ----------------
extern "C" void kernel_launch(void* const* d_in, const int* in_sizes, int n_in,
                              void* d_out, int out_size) {
    const float* x   = (const float*)d_in[0];
    const float* ew  = (const float*)d_in[1];
    const float* Wx  = (const float*)d_in[2];
    const float* bx  = (const float*)d_in[3];
    const float* Wh  = (const float*)d_in[4];
    const float* bh  = (const float*)d_in[5];
    const float* W1  = (const float*)d_in[6];
    const float* b1  = (const float*)d_in[7];
    const float* W2  = (const float*)d_in[8];
    const float* b2  = (const float*)d_in[9];
    const void*  ei  = d_in[10];
    float* out = (float*)d_out;

    probe_kernel<<<1, 1>>>(ei);
    zero_init_kernel<<<(Nn*Nn + 255)/256, 256>>>();
    deg_kernel<<<(Ee + 255)/256, 256>>>(ei, ew);
    dinv_kernel<<<(Nn + 255)/256, 256>>>();
    scatterS_kernel<<<(Ee + 255)/256, 256>>>(ei, ew);
    mega_kernel<<<NCTAS, 256>>>(x, Wx, bx, Wh, bh, W1, b1, W2, b2, out);
}